// round 14
// baseline (speedup 1.0000x reference)
#include <cuda_runtime.h>

#define NN 400
#define NC 1000
#define NB 10
#define NE 800
#define XND 121
#define CF 24
#define DH 128
#define H 64
#define CT 128    // configs per tile
#define PADW 132  // padded stride for 128-wide tiles

typedef unsigned long long ull_t;

// ---- scratch ----
__device__ float g_bufA[(size_t)NN * NC * DH];
__device__ float g_bufB[(size_t)NN * NC * DH];
__device__ float g_base[NN * DH];
__device__ float g_proj[(size_t)NB * NC * DH];
__device__ int   g_adj[NE];
__device__ int   g_off[NN + 1];
__device__ float g_invdeg[NN];
__device__ float g_invcnt[NB];

// ---- packed f32x2 helpers ----
__device__ __forceinline__ ull_t pk2(float x) {
    ull_t r; asm("mov.b64 %0, {%1, %1};" : "=l"(r) : "f"(x)); return r;
}
__device__ __forceinline__ ull_t fma2(ull_t a, ull_t b, ull_t c) {
    ull_t d; asm("fma.rn.f32x2 %0, %1, %2, %3;" : "=l"(d) : "l"(a), "l"(b), "l"(c)); return d;
}
__device__ __forceinline__ void upk(ull_t a, float& lo, float& hi) {
    asm("mov.b64 {%0, %1}, %2;" : "=f"(lo), "=f"(hi) : "l"(a));
}

// ============================================================
// Wide GEMM accumulate: 4f x 16c thread tile, DCHUNK k-steps.
// f0 = lane*4, c0t = warp*16 (8 warps -> 128 configs).
// ============================================================
template<int DCHUNK>
__device__ __forceinline__ void gemm_accum16(const float* __restrict__ xT,
                                             const float* __restrict__ ws,
                                             ull_t (&acc)[4][8], int f0, int c0t) {
    #pragma unroll 4
    for (int k = 0; k < DCHUNK; k++) {
        float4 wv = *(const float4*)(ws + k * DH + f0);
        ull_t w0 = pk2(wv.x), w1 = pk2(wv.y), w2 = pk2(wv.z), w3 = pk2(wv.w);
        const ulonglong2* xr = (const ulonglong2*)(xT + k * PADW + c0t);
        #pragma unroll
        for (int q = 0; q < 4; q++) {
            ulonglong2 xv = xr[q];
            acc[0][2*q]   = fma2(xv.x, w0, acc[0][2*q]);
            acc[1][2*q]   = fma2(xv.x, w1, acc[1][2*q]);
            acc[2][2*q]   = fma2(xv.x, w2, acc[2][2*q]);
            acc[3][2*q]   = fma2(xv.x, w3, acc[3][2*q]);
            acc[0][2*q+1] = fma2(xv.y, w0, acc[0][2*q+1]);
            acc[1][2*q+1] = fma2(xv.y, w1, acc[1][2*q+1]);
            acc[2][2*q+1] = fma2(xv.y, w2, acc[2][2*q+1]);
            acc[3][2*q+1] = fma2(xv.y, w3, acc[3][2*q+1]);
        }
    }
}

__device__ __forceinline__ void acc_init16(ull_t (&acc)[4][8], const float* bs, int f0) {
    float4 bv = *(const float4*)(bs + f0);
    ull_t b0 = pk2(bv.x), b1 = pk2(bv.y), b2_ = pk2(bv.z), b3 = pk2(bv.w);
    #pragma unroll
    for (int p = 0; p < 8; p++) { acc[0][p] = b0; acc[1][p] = b1; acc[2][p] = b2_; acc[3][p] = b3; }
}

__device__ __forceinline__ void gemm_epi16_gmem(ull_t (&acc)[4][8], float* __restrict__ outg,
                                                int f0, int c0t, int span, bool relu) {
    #pragma unroll
    for (int p = 0; p < 8; p++) {
        int c = c0t + 2 * p;
        float lo0, hi0, lo1, hi1, lo2, hi2, lo3, hi3;
        upk(acc[0][p], lo0, hi0); upk(acc[1][p], lo1, hi1);
        upk(acc[2][p], lo2, hi2); upk(acc[3][p], lo3, hi3);
        if (relu) {
            lo0 = fmaxf(lo0, 0.f); hi0 = fmaxf(hi0, 0.f);
            lo1 = fmaxf(lo1, 0.f); hi1 = fmaxf(hi1, 0.f);
            lo2 = fmaxf(lo2, 0.f); hi2 = fmaxf(hi2, 0.f);
            lo3 = fmaxf(lo3, 0.f); hi3 = fmaxf(hi3, 0.f);
        }
        if (c < span)     *(float4*)(outg + (size_t)c * DH + f0)       = make_float4(lo0, lo1, lo2, lo3);
        if (c + 1 < span) *(float4*)(outg + (size_t)(c + 1) * DH + f0) = make_float4(hi0, hi1, hi2, hi3);
    }
}

// ============================================================
// Setup kernels
// ============================================================
__global__ void k_prep(const int* __restrict__ ei, const int* __restrict__ batch) {
    __shared__ int cnt[NN];
    __shared__ int off[NN + 1];
    __shared__ int cur[NN];
    __shared__ int bc[NB];
    int t = threadIdx.x;
    for (int i = t; i < NN; i += blockDim.x) cnt[i] = 0;
    if (t < NB) bc[t] = 0;
    __syncthreads();
    for (int e = t; e < NE; e += blockDim.x) atomicAdd(&cnt[ei[NE + e]], 1);
    for (int i = t; i < NN; i += blockDim.x) atomicAdd(&bc[batch[i]], 1);
    __syncthreads();
    if (t == 0) {
        int s = 0;
        for (int i = 0; i < NN; i++) { off[i] = s; s += cnt[i]; }
        off[NN] = s;
    }
    __syncthreads();
    for (int i = t; i < NN; i += blockDim.x) {
        cur[i] = off[i];
        g_off[i] = off[i];
        g_invdeg[i] = 1.f / fmaxf((float)cnt[i], 1.f);
    }
    if (t == 0) g_off[NN] = off[NN];
    if (t < NB) g_invcnt[t] = 1.f / fmaxf((float)bc[t], 1.f);
    __syncthreads();
    for (int e = t; e < NE; e += blockDim.x) {
        int d = ei[NE + e];
        int p = atomicAdd(&cur[d], 1);
        g_adj[p] = ei[e];
    }
}

__global__ void k_base(const float* __restrict__ node_feat, const int* __restrict__ opcode,
                       const float* __restrict__ op_emb, const float* __restrict__ shape_emb,
                       const float* __restrict__ W1, const float* __restrict__ b1) {
    __shared__ float xns[XND];
    int n = blockIdx.x, t = threadIdx.x;
    if (t < XND) {
        float v;
        if (t < 85) v = node_feat[n * 86 + t];
        else if (t < 89) { int st = (int)node_feat[n * 86 + 85]; v = shape_emb[st * 4 + (t - 85)]; }
        else v = op_emb[opcode[n] * 32 + (t - 89)];
        xns[t] = v;
    }
    __syncthreads();
    float acc = b1[t];
    #pragma unroll 11
    for (int k = 0; k < XND; k++) acc += xns[k] * W1[k * DH + t];
    g_base[n * DH + t] = acc;
}

__global__ void __launch_bounds__(256)
k_proj(const float* __restrict__ cfgf, const float* __restrict__ W1) {
    __shared__ float w1t[CF * DH];
    __shared__ float cfgs[40 * CF];
    const int r0 = blockIdx.x * 40;
    const int t = threadIdx.x;
    for (int e = t; e < CF * DH; e += 256) w1t[e] = W1[XND * DH + e];
    for (int e = t; e < 40 * CF; e += 256) cfgs[e] = cfgf[(size_t)r0 * CF + e];
    __syncthreads();
    const int f = t & 127, rh = t >> 7;
    for (int rr = rh; rr < 40; rr += 2) {
        float acc = 0.f;
        #pragma unroll
        for (int j = 0; j < CF; j++) acc += cfgs[rr * CF + j] * w1t[j * DH + f];
        g_proj[(size_t)(r0 + rr) * DH + f] = acc;
    }
}

// ============================================================
// FUSED layer 0 (128c tile, 4f x 16c, 2 CTAs/SM): R12-measured best.
// ============================================================
__global__ void __launch_bounds__(256, 2)
k_layer0(const int* __restrict__ batch, const float* __restrict__ W2, const float* __restrict__ b2,
         const float* __restrict__ Wl, const float* __restrict__ Wr, const float* __restrict__ bg) {
    extern __shared__ float sm[];
    float* sb  = sm;                   // 128 base
    float* b2s = sm + DH;              // 128
    float* bgs = sm + 2 * DH;          // 128 (bg | 0)
    float* xT  = sm + 3 * DH;          // 128*PADW (x1, later x2)
    float* wch = xT + 128 * PADW;      // 64*128

    const int n = blockIdx.y, c0b = blockIdx.x * CT;
    const int span = min(CT, NC - c0b);
    const int t = threadIdx.x;

    if (t < DH) {
        sb[t]  = g_base[n * DH + t];
        b2s[t] = b2[t];
        bgs[t] = (t < H) ? bg[t] : 0.f;
    }
    for (int e = t; e < 64 * DH; e += 256) wch[e] = W2[e];
    const int bn = batch[n];
    const float* pr = g_proj + ((size_t)bn * NC + c0b) * DH;
    __syncthreads();
    for (int e = t; e < 128 * CT; e += 256) {
        int c = e >> 7, k = e & 127;
        float v = 0.f;
        if (c < span) v = fmaxf(sb[k] + pr[(size_t)c * DH + k], 0.f);
        xT[k * PADW + c] = v;
    }
    __syncthreads();

    const int f0 = (t & 31) * 4, c0t = (t >> 5) * 16;
    ull_t acc[4][8];

    // GEMM1: x2 = relu(x1 @ W2 + b2)
    acc_init16(acc, b2s, f0);
    gemm_accum16<64>(xT, wch, acc, f0, c0t);
    __syncthreads();
    for (int e = t; e < 64 * DH; e += 256) wch[e] = W2[64 * DH + e];
    __syncthreads();
    gemm_accum16<64>(xT + 64 * PADW, wch, acc, f0, c0t);
    __syncthreads();

    #pragma unroll
    for (int p = 0; p < 8; p++) {
        int c = c0t + 2 * p;
        #pragma unroll
        for (int i = 0; i < 4; i++) {
            float lo, hi; upk(acc[i][p], lo, hi);
            *(float2*)(xT + (f0 + i) * PADW + c) = make_float2(fmaxf(lo, 0.f), fmaxf(hi, 0.f));
        }
    }
    for (int e = t; e < 64 * H; e += 256) {
        int k = e / H, f = e - k * H;
        wch[k * DH + f]     = Wl[e];
        wch[k * DH + H + f] = Wr[e];
    }
    __syncthreads();

    // GEMM2: y = (x2@Wl + bg | x2@Wr)
    acc_init16(acc, bgs, f0);
    gemm_accum16<64>(xT, wch, acc, f0, c0t);
    __syncthreads();
    for (int e = t; e < 64 * H; e += 256) {
        int k = e / H, f = e - k * H;
        wch[k * DH + f]     = Wl[(64 + k) * H + f];
        wch[k * DH + H + f] = Wr[(64 + k) * H + f];
    }
    __syncthreads();
    gemm_accum16<64>(xT + 64 * PADW, wch, acc, f0, c0t);

    float* yb = g_bufB + ((size_t)n * NC + c0b) * DH;
    gemm_epi16_gmem(acc, yb, f0, c0t, span, false);
}

// ============================================================
// SAGE proj (D=64): 128c tile, 4f x 16c, 2 CTAs/SM.
// ============================================================
__global__ void __launch_bounds__(256, 2)
k_sageG64(const float* __restrict__ Wl, const float* __restrict__ Wr, const float* __restrict__ bg) {
    extern __shared__ float sm[];
    float* xT = sm;                // 64*PADW
    float* ws = xT + 64 * PADW;    // 64*128
    float* bs = ws + 64 * DH;      // 128
    const int n = blockIdx.y, c0 = blockIdx.x * CT;
    const int span = min(CT, NC - c0);
    const int t = threadIdx.x;

    if (t < DH) bs[t] = (t < H) ? bg[t] : 0.f;
    for (int e = t; e < 64 * H; e += 256) {
        int k = e / H, f = e - k * H;
        ws[k * DH + f]     = Wl[e];
        ws[k * DH + H + f] = Wr[e];
    }
    const float* xb = g_bufA + ((size_t)n * NC + c0) * 64;
    for (int e = t; e < 64 * CT; e += 256) {
        int c = e >> 6, k = e & 63;
        xT[k * PADW + c] = (c < span) ? xb[e] : 0.f;
    }
    __syncthreads();

    const int f0 = (t & 31) * 4, c0t = (t >> 5) * 16;
    ull_t acc[4][8];
    acc_init16(acc, bs, f0);
    gemm_accum16<64>(xT, ws, acc, f0, c0t);

    float* yb = g_bufB + ((size_t)n * NC + c0) * DH;
    gemm_epi16_gmem(acc, yb, f0, c0t, span, false);
}

// ============================================================
// SAGE aggregate (float4): x' = relu(y[dst][0:64] + mean_src y[src][64:128])
// ============================================================
__global__ void k_sageA() {
    const int n = blockIdx.y, c0 = blockIdx.x * CT;
    const int span = min(CT, NC - c0);
    const int o0 = g_off[n], o1 = g_off[n + 1];
    const float inv = g_invdeg[n];
    const int tot = span * 16;
    const float4* yb = (const float4*)(g_bufB + ((size_t)n * NC + c0) * DH);
    float4* xb = (float4*)(g_bufA + ((size_t)n * NC + c0) * H);
    for (int idx = threadIdx.x; idx < tot; idx += 256) {
        int c = idx >> 4, q = idx & 15;
        float4 own = yb[c * 32 + q];
        float4 s = make_float4(0.f, 0.f, 0.f, 0.f);
        for (int e = o0; e < o1; e++) {
            const float4* src = (const float4*)(g_bufB + ((size_t)g_adj[e] * NC + c0 + c) * DH + H);
            float4 v = src[q];
            s.x += v.x; s.y += v.y; s.z += v.z; s.w += v.w;
        }
        float4 r;
        r.x = fmaxf(own.x + s.x * inv, 0.f);
        r.y = fmaxf(own.y + s.y * inv, 0.f);
        r.z = fmaxf(own.z + s.z * inv, 0.f);
        r.w = fmaxf(own.w + s.w * inv, 0.f);
        xb[c * 16 + q] = r;
    }
}

// ============================================================
// Fused pool: aggregate layer-3 from g_bufB on the fly, then
// max+mean pool over 40 nodes, L2-normalize, MLP head -> out[b][c].
// 50-config tiles, grid (20, NB).
// ============================================================
__global__ void __launch_bounds__(256)
k_poolf(const float* __restrict__ Wp1, const float* __restrict__ bp1,
        const float* __restrict__ Wp2, const float* __restrict__ bp2,
        float* __restrict__ out) {
    __shared__ float pooled[50 * 64];
    __shared__ float w1s[64 * 32];
    __shared__ float b1s[32];
    __shared__ float w2s[32];
    __shared__ int   s_off[41];
    __shared__ float s_inv[40];
    const int b = blockIdx.y, c0 = blockIdx.x * 50;
    const int t = threadIdx.x;
    for (int e = t; e < 64 * 32; e += 256) w1s[e] = Wp1[e];
    if (t < 32) { b1s[t] = bp1[t]; w2s[t] = Wp2[t]; }
    if (t < 41) s_off[t] = g_off[b * 40 + t];
    if (t < 40) s_inv[t] = g_invdeg[b * 40 + t];
    __syncthreads();
    const float invc = g_invcnt[b];
    for (int idx = t; idx < 50 * 64; idx += 256) {
        int c = idx >> 6, h = idx & 63;
        size_t rc = (size_t)(c0 + c);
        float mx = -3.4e38f, sum = 0.f;
        for (int i = 0; i < 40; i++) {
            int node = b * 40 + i;
            float v = g_bufB[((size_t)node * NC + rc) * DH + h];
            float s = 0.f;
            for (int e = s_off[i]; e < s_off[i + 1]; e++)
                s += g_bufB[((size_t)g_adj[e] * NC + rc) * DH + H + h];
            v = fmaxf(v + s * s_inv[i], 0.f);
            mx = fmaxf(mx, v);
            sum += v;
        }
        pooled[idx] = mx + sum * invc;
    }
    __syncthreads();
    const int w = t >> 5, lane = t & 31;
    const float bp2v = bp2[0];
    for (int c = w; c < 50; c += 8) {
        float v0 = pooled[c * 64 + lane], v1 = pooled[c * 64 + 32 + lane];
        float ss = v0 * v0 + v1 * v1;
        #pragma unroll
        for (int m = 16; m; m >>= 1) ss += __shfl_xor_sync(0xffffffffu, ss, m);
        float inv = rsqrtf(ss);
        float dot = 0.f;
        #pragma unroll
        for (int h = 0; h < 64; h++) dot += pooled[c * 64 + h] * w1s[h * 32 + lane];
        float hj = fmaxf(b1s[lane] + inv * dot, 0.f);
        float o = hj * w2s[lane];
        #pragma unroll
        for (int m = 16; m; m >>= 1) o += __shfl_xor_sync(0xffffffffu, o, m);
        if (lane == 0) out[b * NC + c0 + c] = o + bp2v;
    }
}

// ============================================================
extern "C" void kernel_launch(void* const* d_in, const int* in_sizes, int n_in,
                              void* d_out, int out_size) {
    const float* node_feat   = (const float*)d_in[0];
    const int*   node_opcode = (const int*)d_in[1];
    const float* config_feat = (const float*)d_in[2];
    const int*   edge_index  = (const int*)d_in[3];
    const int*   batch       = (const int*)d_in[4];
    const float* op_emb      = (const float*)d_in[5];
    const float* shape_emb   = (const float*)d_in[6];
    const float* W1  = (const float*)d_in[7];
    const float* b1  = (const float*)d_in[8];
    const float* W2  = (const float*)d_in[9];
    const float* b2  = (const float*)d_in[10];
    const float* Wl0 = (const float*)d_in[11];
    const float* Wr0 = (const float*)d_in[12];
    const float* bg0 = (const float*)d_in[13];
    const float* Wl1 = (const float*)d_in[14];
    const float* Wr1 = (const float*)d_in[15];
    const float* bg1 = (const float*)d_in[16];
    const float* Wl2 = (const float*)d_in[17];
    const float* Wr2 = (const float*)d_in[18];
    const float* bg2 = (const float*)d_in[19];
    const float* Wp1 = (const float*)d_in[20];
    const float* bp1 = (const float*)d_in[21];
    const float* Wp2 = (const float*)d_in[22];
    const float* bp2 = (const float*)d_in[23];
    float* out = (float*)d_out;

    const int SM_L0  = (3 * DH + 128 * PADW + 64 * DH) * 4;   // ~99.5 KB (x2 CTAs)
    const int SM_G64 = (64 * PADW + 64 * DH + DH) * 4;        // ~67 KB (x2 CTAs)
    cudaFuncSetAttribute(k_layer0,  cudaFuncAttributeMaxDynamicSharedMemorySize, SM_L0);
    cudaFuncSetAttribute(k_sageG64, cudaFuncAttributeMaxDynamicSharedMemorySize, SM_G64);

    k_prep<<<1, 512>>>(edge_index, batch);
    k_base<<<NN, 128>>>(node_feat, node_opcode, op_emb, shape_emb, W1, b1);
    k_proj<<<250, 256>>>(config_feat, W1);

    dim3 g128t(8, NN);
    k_layer0<<<g128t, 256, SM_L0>>>(batch, W2, b2, Wl0, Wr0, bg0);  // -> bufB

    k_sageA<<<g128t, 256>>>();                                      // bufB -> bufA
    k_sageG64<<<g128t, 256, SM_G64>>>(Wl1, Wr1, bg1);               // bufA -> bufB
    k_sageA<<<g128t, 256>>>();                                      // bufB -> bufA
    k_sageG64<<<g128t, 256, SM_G64>>>(Wl2, Wr2, bg2);               // bufA -> bufB

    dim3 gpool(20, NB);
    k_poolf<<<gpool, 256>>>(Wp1, bp1, Wp2, bp2, out);               // agg bufB -> pool -> head
}

// round 15
// speedup vs baseline: 1.2319x; 1.2319x over previous
#include <cuda_runtime.h>

#define NN 400
#define NC 1000
#define NB 10
#define NE 800
#define XND 121
#define CF 24
#define DH 128
#define H 64
#define CT 128    // configs per tile (sageA, sageG64)
#define PADW 132  // padded stride for 128-wide tiles
#define CT64 64   // configs per tile (k_layer0)
#define PAD64 68  // padded stride for 64-wide tiles

typedef unsigned long long ull_t;

// ---- scratch ----
__device__ float g_bufA[(size_t)NN * NC * DH];
__device__ float g_bufB[(size_t)NN * NC * DH];
__device__ float g_base[NN * DH];
__device__ float g_proj[(size_t)NB * NC * DH];
__device__ int   g_adj[NE];
__device__ int   g_off[NN + 1];
__device__ float g_invdeg[NN];
__device__ float g_invcnt[NB];

// ---- packed f32x2 helpers ----
__device__ __forceinline__ ull_t pk2(float x) {
    ull_t r; asm("mov.b64 %0, {%1, %1};" : "=l"(r) : "f"(x)); return r;
}
__device__ __forceinline__ ull_t fma2(ull_t a, ull_t b, ull_t c) {
    ull_t d; asm("fma.rn.f32x2 %0, %1, %2, %3;" : "=l"(d) : "l"(a), "l"(b), "l"(c)); return d;
}
__device__ __forceinline__ void upk(ull_t a, float& lo, float& hi) {
    asm("mov.b64 {%0, %1}, %2;" : "=f"(lo), "=f"(hi) : "l"(a));
}

// ============================================================
// GEMM accumulate over DCHUNK k-steps. Thread tile 4f x 8c.
// f0 = lane*4, c0 = warp*8. xT stride PAD64.
// ============================================================
template<int DCHUNK>
__device__ __forceinline__ void gemm_accum(const float* __restrict__ xT,
                                           const float* __restrict__ ws,
                                           ull_t (&acc)[4][4], int f0, int c0) {
    #pragma unroll 4
    for (int k = 0; k < DCHUNK; k++) {
        float4 wv = *(const float4*)(ws + k * DH + f0);
        ull_t w0 = pk2(wv.x), w1 = pk2(wv.y), w2 = pk2(wv.z), w3 = pk2(wv.w);
        const ulonglong2* xr = (const ulonglong2*)(xT + k * PAD64 + c0);
        ulonglong2 xA = xr[0], xB = xr[1];
        acc[0][0] = fma2(xA.x, w0, acc[0][0]);
        acc[1][0] = fma2(xA.x, w1, acc[1][0]);
        acc[2][0] = fma2(xA.x, w2, acc[2][0]);
        acc[3][0] = fma2(xA.x, w3, acc[3][0]);
        acc[0][1] = fma2(xA.y, w0, acc[0][1]);
        acc[1][1] = fma2(xA.y, w1, acc[1][1]);
        acc[2][1] = fma2(xA.y, w2, acc[2][1]);
        acc[3][1] = fma2(xA.y, w3, acc[3][1]);
        acc[0][2] = fma2(xB.x, w0, acc[0][2]);
        acc[1][2] = fma2(xB.x, w1, acc[1][2]);
        acc[2][2] = fma2(xB.x, w2, acc[2][2]);
        acc[3][2] = fma2(xB.x, w3, acc[3][2]);
        acc[0][3] = fma2(xB.y, w0, acc[0][3]);
        acc[1][3] = fma2(xB.y, w1, acc[1][3]);
        acc[2][3] = fma2(xB.y, w2, acc[2][3]);
        acc[3][3] = fma2(xB.y, w3, acc[3][3]);
    }
}

__device__ __forceinline__ void acc_init(ull_t (&acc)[4][4], const float* bs, int f0) {
    float4 bv = *(const float4*)(bs + f0);
    ull_t b0 = pk2(bv.x), b1 = pk2(bv.y), b2_ = pk2(bv.z), b3 = pk2(bv.w);
    #pragma unroll
    for (int p = 0; p < 4; p++) { acc[0][p] = b0; acc[1][p] = b1; acc[2][p] = b2_; acc[3][p] = b3; }
}

__device__ __forceinline__ void gemm_epilogue_gmem(ull_t (&acc)[4][4], float* __restrict__ outg,
                                                   int f0, int c0, int span, bool relu) {
    #pragma unroll
    for (int p = 0; p < 4; p++) {
        int c = c0 + 2 * p;
        float lo0, hi0, lo1, hi1, lo2, hi2, lo3, hi3;
        upk(acc[0][p], lo0, hi0); upk(acc[1][p], lo1, hi1);
        upk(acc[2][p], lo2, hi2); upk(acc[3][p], lo3, hi3);
        if (relu) {
            lo0 = fmaxf(lo0, 0.f); hi0 = fmaxf(hi0, 0.f);
            lo1 = fmaxf(lo1, 0.f); hi1 = fmaxf(hi1, 0.f);
            lo2 = fmaxf(lo2, 0.f); hi2 = fmaxf(hi2, 0.f);
            lo3 = fmaxf(lo3, 0.f); hi3 = fmaxf(hi3, 0.f);
        }
        if (c < span)     *(float4*)(outg + (size_t)c * DH + f0)       = make_float4(lo0, lo1, lo2, lo3);
        if (c + 1 < span) *(float4*)(outg + (size_t)(c + 1) * DH + f0) = make_float4(hi0, hi1, hi2, hi3);
    }
}

// ============================================================
// Setup kernels
// ============================================================
__global__ void k_prep(const int* __restrict__ ei, const int* __restrict__ batch) {
    __shared__ int cnt[NN];
    __shared__ int off[NN + 1];
    __shared__ int cur[NN];
    __shared__ int bc[NB];
    int t = threadIdx.x;
    for (int i = t; i < NN; i += blockDim.x) cnt[i] = 0;
    if (t < NB) bc[t] = 0;
    __syncthreads();
    for (int e = t; e < NE; e += blockDim.x) atomicAdd(&cnt[ei[NE + e]], 1);
    for (int i = t; i < NN; i += blockDim.x) atomicAdd(&bc[batch[i]], 1);
    __syncthreads();
    if (t == 0) {
        int s = 0;
        for (int i = 0; i < NN; i++) { off[i] = s; s += cnt[i]; }
        off[NN] = s;
    }
    __syncthreads();
    for (int i = t; i < NN; i += blockDim.x) {
        cur[i] = off[i];
        g_off[i] = off[i];
        g_invdeg[i] = 1.f / fmaxf((float)cnt[i], 1.f);
    }
    if (t == 0) g_off[NN] = off[NN];
    if (t < NB) g_invcnt[t] = 1.f / fmaxf((float)bc[t], 1.f);
    __syncthreads();
    for (int e = t; e < NE; e += blockDim.x) {
        int d = ei[NE + e];
        int p = atomicAdd(&cur[d], 1);
        g_adj[p] = ei[e];
    }
}

__global__ void k_base(const float* __restrict__ node_feat, const int* __restrict__ opcode,
                       const float* __restrict__ op_emb, const float* __restrict__ shape_emb,
                       const float* __restrict__ W1, const float* __restrict__ b1) {
    __shared__ float xns[XND];
    int n = blockIdx.x, t = threadIdx.x;
    if (t < XND) {
        float v;
        if (t < 85) v = node_feat[n * 86 + t];
        else if (t < 89) { int st = (int)node_feat[n * 86 + 85]; v = shape_emb[st * 4 + (t - 85)]; }
        else v = op_emb[opcode[n] * 32 + (t - 89)];
        xns[t] = v;
    }
    __syncthreads();
    float acc = b1[t];
    #pragma unroll 11
    for (int k = 0; k < XND; k++) acc += xns[k] * W1[k * DH + t];
    g_base[n * DH + t] = acc;
}

__global__ void __launch_bounds__(256)
k_proj(const float* __restrict__ cfgf, const float* __restrict__ W1) {
    __shared__ float w1t[CF * DH];
    __shared__ float cfgs[40 * CF];
    const int r0 = blockIdx.x * 40;
    const int t = threadIdx.x;
    for (int e = t; e < CF * DH; e += 256) w1t[e] = W1[XND * DH + e];
    for (int e = t; e < 40 * CF; e += 256) cfgs[e] = cfgf[(size_t)r0 * CF + e];
    __syncthreads();
    const int f = t & 127, rh = t >> 7;
    for (int rr = rh; rr < 40; rr += 2) {
        float acc = 0.f;
        #pragma unroll
        for (int j = 0; j < CF; j++) acc += cfgs[rr * CF + j] * w1t[j * DH + f];
        g_proj[(size_t)(r0 + rr) * DH + f] = acc;
    }
}

// ============================================================
// FUSED layer 0: x1 = relu(base + proj); x2 = relu(x1@W2 + b2) [smem,
// written back into x1's tile]; y = (x2@Wl0 + bg0 | x2@Wr0) -> g_bufB.
// 64c tile, 3 CTAs/SM (R11-measured best config).
// ============================================================
__global__ void __launch_bounds__(256, 3)
k_layer0(const int* __restrict__ batch, const float* __restrict__ W2, const float* __restrict__ b2,
         const float* __restrict__ Wl, const float* __restrict__ Wr, const float* __restrict__ bg) {
    extern __shared__ float sm[];
    float* sb  = sm;                   // 128 base
    float* b2s = sm + DH;              // 128
    float* bgs = sm + 2 * DH;          // 128 (bg | 0)
    float* xT  = sm + 3 * DH;          // 128*PAD64 (x1, later x2)
    float* wch = xT + 128 * PAD64;     // 64*128

    const int n = blockIdx.y, c0b = blockIdx.x * CT64;
    const int span = min(CT64, NC - c0b);
    const int t = threadIdx.x;

    if (t < DH) {
        sb[t]  = g_base[n * DH + t];
        b2s[t] = b2[t];
        bgs[t] = (t < H) ? bg[t] : 0.f;
    }
    for (int e = t; e < 64 * DH; e += 256) wch[e] = W2[e];
    const int bn = batch[n];
    const float* pr = g_proj + ((size_t)bn * NC + c0b) * DH;
    __syncthreads();
    for (int e = t; e < 128 * CT64; e += 256) {
        int c = e >> 7, k = e & 127;
        float v = 0.f;
        if (c < span) v = fmaxf(sb[k] + pr[(size_t)c * DH + k], 0.f);
        xT[k * PAD64 + c] = v;
    }
    __syncthreads();

    const int f0 = (t & 31) * 4, c0 = (t >> 5) * 8;
    ull_t acc[4][4];

    // GEMM1: x2 = relu(x1 @ W2 + b2)
    acc_init(acc, b2s, f0);
    gemm_accum<64>(xT, wch, acc, f0, c0);
    __syncthreads();
    for (int e = t; e < 64 * DH; e += 256) wch[e] = W2[64 * DH + e];
    __syncthreads();
    gemm_accum<64>(xT + 64 * PAD64, wch, acc, f0, c0);
    __syncthreads();

    #pragma unroll
    for (int p = 0; p < 4; p++) {
        int c = c0 + 2 * p;
        #pragma unroll
        for (int i = 0; i < 4; i++) {
            float lo, hi; upk(acc[i][p], lo, hi);
            *(float2*)(xT + (f0 + i) * PAD64 + c) = make_float2(fmaxf(lo, 0.f), fmaxf(hi, 0.f));
        }
    }
    for (int e = t; e < 64 * H; e += 256) {
        int k = e / H, f = e - k * H;
        wch[k * DH + f]     = Wl[e];
        wch[k * DH + H + f] = Wr[e];
    }
    __syncthreads();

    // GEMM2: y = (x2@Wl + bg | x2@Wr)
    acc_init(acc, bgs, f0);
    gemm_accum<64>(xT, wch, acc, f0, c0);
    __syncthreads();
    for (int e = t; e < 64 * H; e += 256) {
        int k = e / H, f = e - k * H;
        wch[k * DH + f]     = Wl[(64 + k) * H + f];
        wch[k * DH + H + f] = Wr[(64 + k) * H + f];
    }
    __syncthreads();
    gemm_accum<64>(xT + 64 * PAD64, wch, acc, f0, c0);

    float* yb = g_bufB + ((size_t)n * NC + c0b) * DH;
    gemm_epilogue_gmem(acc, yb, f0, c0, span, false);
}

// ============================================================
// SAGE proj (D=64): 128c tile, 4f x 16c, 2 CTAs/SM (R7/R11-proven).
// Reads g_bufA[...][64], writes g_bufB = (x@Wl + bg | x@Wr).
// ============================================================
__global__ void __launch_bounds__(256, 2)
k_sageG64(const float* __restrict__ Wl, const float* __restrict__ Wr, const float* __restrict__ bg) {
    extern __shared__ float sm[];
    float* xT = sm;                // 64*PADW
    float* ws = xT + 64 * PADW;    // 64*128
    float* bs = ws + 64 * DH;      // 128
    const int n = blockIdx.y, c0 = blockIdx.x * CT;
    const int span = min(CT, NC - c0);
    const int t = threadIdx.x;

    if (t < DH) bs[t] = (t < H) ? bg[t] : 0.f;
    for (int e = t; e < 64 * H; e += 256) {
        int k = e / H, f = e - k * H;
        ws[k * DH + f]     = Wl[e];
        ws[k * DH + H + f] = Wr[e];
    }
    const float* xb = g_bufA + ((size_t)n * NC + c0) * 64;
    for (int e = t; e < 64 * CT; e += 256) {
        int c = e >> 6, k = e & 63;
        xT[k * PADW + c] = (c < span) ? xb[e] : 0.f;
    }
    __syncthreads();

    const int f0 = (t & 31) * 4;
    const int c0t = (t >> 5) * 16;
    ull_t acc[4][8];
    {
        float4 bv = *(const float4*)(bs + f0);
        ull_t b0 = pk2(bv.x), b1 = pk2(bv.y), b2_ = pk2(bv.z), b3 = pk2(bv.w);
        #pragma unroll
        for (int p = 0; p < 8; p++) { acc[0][p] = b0; acc[1][p] = b1; acc[2][p] = b2_; acc[3][p] = b3; }
    }
    #pragma unroll 4
    for (int k = 0; k < 64; k++) {
        float4 wv = *(const float4*)(ws + k * DH + f0);
        ull_t w0 = pk2(wv.x), w1 = pk2(wv.y), w2 = pk2(wv.z), w3 = pk2(wv.w);
        const ulonglong2* xr = (const ulonglong2*)(xT + k * PADW + c0t);
        #pragma unroll
        for (int q = 0; q < 4; q++) {
            ulonglong2 xv = xr[q];
            acc[0][2*q]   = fma2(xv.x, w0, acc[0][2*q]);
            acc[1][2*q]   = fma2(xv.x, w1, acc[1][2*q]);
            acc[2][2*q]   = fma2(xv.x, w2, acc[2][2*q]);
            acc[3][2*q]   = fma2(xv.x, w3, acc[3][2*q]);
            acc[0][2*q+1] = fma2(xv.y, w0, acc[0][2*q+1]);
            acc[1][2*q+1] = fma2(xv.y, w1, acc[1][2*q+1]);
            acc[2][2*q+1] = fma2(xv.y, w2, acc[2][2*q+1]);
            acc[3][2*q+1] = fma2(xv.y, w3, acc[3][2*q+1]);
        }
    }
    float* yb = g_bufB + ((size_t)n * NC + c0) * DH;
    #pragma unroll
    for (int p = 0; p < 8; p++) {
        int c = c0t + 2 * p;
        float lo0, hi0, lo1, hi1, lo2, hi2, lo3, hi3;
        upk(acc[0][p], lo0, hi0); upk(acc[1][p], lo1, hi1);
        upk(acc[2][p], lo2, hi2); upk(acc[3][p], lo3, hi3);
        if (c < span)     *(float4*)(yb + (size_t)c * DH + f0)       = make_float4(lo0, lo1, lo2, lo3);
        if (c + 1 < span) *(float4*)(yb + (size_t)(c + 1) * DH + f0) = make_float4(hi0, hi1, hi2, hi3);
    }
}

// ============================================================
// SAGE aggregate, MLP-8: edge loop OUTER, 8 independent float4
// gathers per edge. x' = relu(y[dst][0:64] + mean_src y[src][64:128]).
// ============================================================
__global__ void __launch_bounds__(256)
k_sageA() {
    const int n = blockIdx.y, c0 = blockIdx.x * CT;
    const int span = min(CT, NC - c0);
    const int o0 = g_off[n], o1 = g_off[n + 1];
    const float inv = g_invdeg[n];
    const int tot = span * 16;  // float4 units
    const int t = threadIdx.x;

    const float4* yb = (const float4*)(g_bufB + ((size_t)n * NC + c0) * DH);
    float4* xb = (float4*)(g_bufA + ((size_t)n * NC + c0) * H);

    int cc[8]; int qq[8]; bool val[8];
    float4 own[8]; float4 acc[8];
    #pragma unroll
    for (int j = 0; j < 8; j++) {
        int idx = t + j * 256;
        val[j] = idx < tot;
        cc[j] = idx >> 4;
        qq[j] = idx & 15;
        own[j] = val[j] ? yb[cc[j] * 32 + qq[j]] : make_float4(0.f, 0.f, 0.f, 0.f);
        acc[j] = make_float4(0.f, 0.f, 0.f, 0.f);
    }

    for (int e = o0; e < o1; e++) {
        const float4* src = (const float4*)(g_bufB + ((size_t)g_adj[e] * NC + c0) * DH + H);
        #pragma unroll
        for (int j = 0; j < 8; j++) {
            if (val[j]) {
                float4 v = src[cc[j] * 32 + qq[j]];
                acc[j].x += v.x; acc[j].y += v.y; acc[j].z += v.z; acc[j].w += v.w;
            }
        }
    }

    #pragma unroll
    for (int j = 0; j < 8; j++) {
        if (val[j]) {
            float4 r;
            r.x = fmaxf(own[j].x + acc[j].x * inv, 0.f);
            r.y = fmaxf(own[j].y + acc[j].y * inv, 0.f);
            r.z = fmaxf(own[j].z + acc[j].z * inv, 0.f);
            r.w = fmaxf(own[j].w + acc[j].w * inv, 0.f);
            xb[cc[j] * 16 + qq[j]] = r;
        }
    }
}

// ============================================================
// Pool (max + mean over 40 nodes), L2-normalize, MLP head
// ============================================================
__global__ void __launch_bounds__(256)
k_pool(const float* __restrict__ Wp1, const float* __restrict__ bp1,
       const float* __restrict__ Wp2, const float* __restrict__ bp2,
       float* __restrict__ out) {
    __shared__ float pooled[100 * 64];
    __shared__ float w1s[64 * 32];
    __shared__ float b1s[32];
    __shared__ float w2s[32];
    const int b = blockIdx.y, c0 = blockIdx.x * 100;
    const int t = threadIdx.x;
    for (int e = t; e < 64 * 32; e += 256) w1s[e] = Wp1[e];
    if (t < 32) { b1s[t] = bp1[t]; w2s[t] = Wp2[t]; }
    const float invc = g_invcnt[b];
    const float* xb = g_bufA + ((size_t)(b * 40) * NC + c0) * H;
    for (int idx = t; idx < 100 * 64; idx += 256) {
        int c = idx >> 6, h = idx & 63;
        float mx = -3.4e38f, sm_ = 0.f;
        for (int i = 0; i < 40; i++) {
            float v = xb[((size_t)i * NC + c) * H + h];
            mx = fmaxf(mx, v);
            sm_ += v;
        }
        pooled[idx] = mx + sm_ * invc;
    }
    __syncthreads();
    const int w = t >> 5, lane = t & 31;
    const float bp2v = bp2[0];
    for (int c = w; c < 100; c += 8) {
        float v0 = pooled[c * 64 + lane], v1 = pooled[c * 64 + 32 + lane];
        float ss = v0 * v0 + v1 * v1;
        #pragma unroll
        for (int m = 16; m; m >>= 1) ss += __shfl_xor_sync(0xffffffffu, ss, m);
        float inv = rsqrtf(ss);
        float dot = 0.f;
        #pragma unroll
        for (int h = 0; h < 64; h++) dot += pooled[c * 64 + h] * w1s[h * 32 + lane];
        float hj = fmaxf(b1s[lane] + inv * dot, 0.f);
        float o = hj * w2s[lane];
        #pragma unroll
        for (int m = 16; m; m >>= 1) o += __shfl_xor_sync(0xffffffffu, o, m);
        if (lane == 0) out[b * NC + c0 + c] = o + bp2v;
    }
}

// ============================================================
extern "C" void kernel_launch(void* const* d_in, const int* in_sizes, int n_in,
                              void* d_out, int out_size) {
    const float* node_feat   = (const float*)d_in[0];
    const int*   node_opcode = (const int*)d_in[1];
    const float* config_feat = (const float*)d_in[2];
    const int*   edge_index  = (const int*)d_in[3];
    const int*   batch       = (const int*)d_in[4];
    const float* op_emb      = (const float*)d_in[5];
    const float* shape_emb   = (const float*)d_in[6];
    const float* W1  = (const float*)d_in[7];
    const float* b1  = (const float*)d_in[8];
    const float* W2  = (const float*)d_in[9];
    const float* b2  = (const float*)d_in[10];
    const float* Wl0 = (const float*)d_in[11];
    const float* Wr0 = (const float*)d_in[12];
    const float* bg0 = (const float*)d_in[13];
    const float* Wl1 = (const float*)d_in[14];
    const float* Wr1 = (const float*)d_in[15];
    const float* bg1 = (const float*)d_in[16];
    const float* Wl2 = (const float*)d_in[17];
    const float* Wr2 = (const float*)d_in[18];
    const float* bg2 = (const float*)d_in[19];
    const float* Wp1 = (const float*)d_in[20];
    const float* bp1 = (const float*)d_in[21];
    const float* Wp2 = (const float*)d_in[22];
    const float* bp2 = (const float*)d_in[23];
    float* out = (float*)d_out;

    const int SM_L0  = (3 * DH + 128 * PAD64 + 64 * DH) * 4;   // 69.1 KB (x3 CTAs)
    const int SM_G64 = (64 * PADW + 64 * DH + DH) * 4;         // ~67 KB (x2 CTAs)
    cudaFuncSetAttribute(k_layer0,  cudaFuncAttributeMaxDynamicSharedMemorySize, SM_L0);
    cudaFuncSetAttribute(k_sageG64, cudaFuncAttributeMaxDynamicSharedMemorySize, SM_G64);

    k_prep<<<1, 512>>>(edge_index, batch);
    k_base<<<NN, 128>>>(node_feat, node_opcode, op_emb, shape_emb, W1, b1);
    k_proj<<<250, 256>>>(config_feat, W1);

    dim3 g64t(16, NN);
    k_layer0<<<g64t, 256, SM_L0>>>(batch, W2, b2, Wl0, Wr0, bg0);  // -> bufB

    dim3 g128t(8, NN);
    k_sageA<<<g128t, 256>>>();                                     // bufB -> bufA
    k_sageG64<<<g128t, 256, SM_G64>>>(Wl1, Wr1, bg1);              // bufA -> bufB
    k_sageA<<<g128t, 256>>>();                                     // bufB -> bufA
    k_sageG64<<<g128t, 256, SM_G64>>>(Wl2, Wr2, bg2);              // bufA -> bufB
    k_sageA<<<g128t, 256>>>();                                     // bufB -> bufA

    dim3 gpool(10, NB);
    k_pool<<<gpool, 256>>>(Wp1, bp1, Wp2, bp2, out);
}

// round 16
// speedup vs baseline: 1.2708x; 1.0315x over previous
#include <cuda_runtime.h>

#define NN 400
#define NC 1000
#define NB 10
#define NE 800
#define XND 121
#define CF 24
#define DH 128
#define H 64
#define CT 128    // configs per tile
#define PADW 132  // padded stride for 128-wide tiles

typedef unsigned long long ull_t;

// ---- scratch ----
__device__ float g_bufA[(size_t)NN * NC * DH];
__device__ float g_bufB[(size_t)NN * NC * DH];
__device__ float g_base[NN * DH];
__device__ float g_proj[(size_t)NB * NC * DH];
__device__ int   g_adj[NE];
__device__ int   g_off[NN + 1];
__device__ float g_invdeg[NN];
__device__ float g_invcnt[NB];

// ---- packed f32x2 helpers ----
__device__ __forceinline__ ull_t pk2(float x) {
    ull_t r; asm("mov.b64 %0, {%1, %1};" : "=l"(r) : "f"(x)); return r;
}
__device__ __forceinline__ ull_t fma2(ull_t a, ull_t b, ull_t c) {
    ull_t d; asm("fma.rn.f32x2 %0, %1, %2, %3;" : "=l"(d) : "l"(a), "l"(b), "l"(c)); return d;
}
__device__ __forceinline__ void upk(ull_t a, float& lo, float& hi) {
    asm("mov.b64 {%0, %1}, %2;" : "=f"(lo), "=f"(hi) : "l"(a));
}

// ============================================================
// Wide GEMM accumulate: 4f x 16c thread tile, DCHUNK k-steps.
// f0 = lane*4, c0t = warp*16 (8 warps -> 128 configs). xT stride PADW.
// ============================================================
template<int DCHUNK>
__device__ __forceinline__ void gemm_accum16(const float* __restrict__ xT,
                                             const float* __restrict__ ws,
                                             ull_t (&acc)[4][8], int f0, int c0t) {
    #pragma unroll 4
    for (int k = 0; k < DCHUNK; k++) {
        float4 wv = *(const float4*)(ws + k * DH + f0);
        ull_t w0 = pk2(wv.x), w1 = pk2(wv.y), w2 = pk2(wv.z), w3 = pk2(wv.w);
        const ulonglong2* xr = (const ulonglong2*)(xT + k * PADW + c0t);
        #pragma unroll
        for (int q = 0; q < 4; q++) {
            ulonglong2 xv = xr[q];
            acc[0][2*q]   = fma2(xv.x, w0, acc[0][2*q]);
            acc[1][2*q]   = fma2(xv.x, w1, acc[1][2*q]);
            acc[2][2*q]   = fma2(xv.x, w2, acc[2][2*q]);
            acc[3][2*q]   = fma2(xv.x, w3, acc[3][2*q]);
            acc[0][2*q+1] = fma2(xv.y, w0, acc[0][2*q+1]);
            acc[1][2*q+1] = fma2(xv.y, w1, acc[1][2*q+1]);
            acc[2][2*q+1] = fma2(xv.y, w2, acc[2][2*q+1]);
            acc[3][2*q+1] = fma2(xv.y, w3, acc[3][2*q+1]);
        }
    }
}

__device__ __forceinline__ void acc_init16(ull_t (&acc)[4][8], const float* bs, int f0) {
    float4 bv = *(const float4*)(bs + f0);
    ull_t b0 = pk2(bv.x), b1 = pk2(bv.y), b2_ = pk2(bv.z), b3 = pk2(bv.w);
    #pragma unroll
    for (int p = 0; p < 8; p++) { acc[0][p] = b0; acc[1][p] = b1; acc[2][p] = b2_; acc[3][p] = b3; }
}

__device__ __forceinline__ void gemm_epi16_gmem(ull_t (&acc)[4][8], float* __restrict__ outg,
                                                int f0, int c0t, int span, bool relu) {
    #pragma unroll
    for (int p = 0; p < 8; p++) {
        int c = c0t + 2 * p;
        float lo0, hi0, lo1, hi1, lo2, hi2, lo3, hi3;
        upk(acc[0][p], lo0, hi0); upk(acc[1][p], lo1, hi1);
        upk(acc[2][p], lo2, hi2); upk(acc[3][p], lo3, hi3);
        if (relu) {
            lo0 = fmaxf(lo0, 0.f); hi0 = fmaxf(hi0, 0.f);
            lo1 = fmaxf(lo1, 0.f); hi1 = fmaxf(hi1, 0.f);
            lo2 = fmaxf(lo2, 0.f); hi2 = fmaxf(hi2, 0.f);
            lo3 = fmaxf(lo3, 0.f); hi3 = fmaxf(hi3, 0.f);
        }
        if (c < span)     *(float4*)(outg + (size_t)c * DH + f0)       = make_float4(lo0, lo1, lo2, lo3);
        if (c + 1 < span) *(float4*)(outg + (size_t)(c + 1) * DH + f0) = make_float4(hi0, hi1, hi2, hi3);
    }
}

// ============================================================
// Setup kernels
// ============================================================
__global__ void k_prep(const int* __restrict__ ei, const int* __restrict__ batch) {
    __shared__ int cnt[NN];
    __shared__ int off[NN + 1];
    __shared__ int cur[NN];
    __shared__ int bc[NB];
    int t = threadIdx.x;
    for (int i = t; i < NN; i += blockDim.x) cnt[i] = 0;
    if (t < NB) bc[t] = 0;
    __syncthreads();
    for (int e = t; e < NE; e += blockDim.x) atomicAdd(&cnt[ei[NE + e]], 1);
    for (int i = t; i < NN; i += blockDim.x) atomicAdd(&bc[batch[i]], 1);
    __syncthreads();
    if (t == 0) {
        int s = 0;
        for (int i = 0; i < NN; i++) { off[i] = s; s += cnt[i]; }
        off[NN] = s;
    }
    __syncthreads();
    for (int i = t; i < NN; i += blockDim.x) {
        cur[i] = off[i];
        g_off[i] = off[i];
        g_invdeg[i] = 1.f / fmaxf((float)cnt[i], 1.f);
    }
    if (t == 0) g_off[NN] = off[NN];
    if (t < NB) g_invcnt[t] = 1.f / fmaxf((float)bc[t], 1.f);
    __syncthreads();
    for (int e = t; e < NE; e += blockDim.x) {
        int d = ei[NE + e];
        int p = atomicAdd(&cur[d], 1);
        g_adj[p] = ei[e];
    }
}

__global__ void k_base(const float* __restrict__ node_feat, const int* __restrict__ opcode,
                       const float* __restrict__ op_emb, const float* __restrict__ shape_emb,
                       const float* __restrict__ W1, const float* __restrict__ b1) {
    __shared__ float xns[XND];
    int n = blockIdx.x, t = threadIdx.x;
    if (t < XND) {
        float v;
        if (t < 85) v = node_feat[n * 86 + t];
        else if (t < 89) { int st = (int)node_feat[n * 86 + 85]; v = shape_emb[st * 4 + (t - 85)]; }
        else v = op_emb[opcode[n] * 32 + (t - 89)];
        xns[t] = v;
    }
    __syncthreads();
    float acc = b1[t];
    #pragma unroll 11
    for (int k = 0; k < XND; k++) acc += xns[k] * W1[k * DH + t];
    g_base[n * DH + t] = acc;
}

__global__ void __launch_bounds__(256)
k_proj(const float* __restrict__ cfgf, const float* __restrict__ W1) {
    __shared__ float w1t[CF * DH];
    __shared__ float cfgs[40 * CF];
    const int r0 = blockIdx.x * 40;
    const int t = threadIdx.x;
    for (int e = t; e < CF * DH; e += 256) w1t[e] = W1[XND * DH + e];
    for (int e = t; e < 40 * CF; e += 256) cfgs[e] = cfgf[(size_t)r0 * CF + e];
    __syncthreads();
    const int f = t & 127, rh = t >> 7;
    for (int rr = rh; rr < 40; rr += 2) {
        float acc = 0.f;
        #pragma unroll
        for (int j = 0; j < CF; j++) acc += cfgs[rr * CF + j] * w1t[j * DH + f];
        g_proj[(size_t)(r0 + rr) * DH + f] = acc;
    }
}

// ============================================================
// FUSED layer 0 (128c tile, 4f x 16c, 2 CTAs/SM) — R12-measured 589us.
// x1 = relu(base + proj); x2 = relu(x1@W2 + b2) [back into x1's tile];
// y = (x2@Wl0 + bg0 | x2@Wr0) -> g_bufB.
// ============================================================
__global__ void __launch_bounds__(256, 2)
k_layer0(const int* __restrict__ batch, const float* __restrict__ W2, const float* __restrict__ b2,
         const float* __restrict__ Wl, const float* __restrict__ Wr, const float* __restrict__ bg) {
    extern __shared__ float sm[];
    float* sb  = sm;                   // 128 base
    float* b2s = sm + DH;              // 128
    float* bgs = sm + 2 * DH;          // 128 (bg | 0)
    float* xT  = sm + 3 * DH;          // 128*PADW (x1, later x2)
    float* wch = xT + 128 * PADW;      // 64*128

    const int n = blockIdx.y, c0b = blockIdx.x * CT;
    const int span = min(CT, NC - c0b);
    const int t = threadIdx.x;

    if (t < DH) {
        sb[t]  = g_base[n * DH + t];
        b2s[t] = b2[t];
        bgs[t] = (t < H) ? bg[t] : 0.f;
    }
    for (int e = t; e < 64 * DH; e += 256) wch[e] = W2[e];
    const int bn = batch[n];
    const float* pr = g_proj + ((size_t)bn * NC + c0b) * DH;
    __syncthreads();
    for (int e = t; e < 128 * CT; e += 256) {
        int c = e >> 7, k = e & 127;
        float v = 0.f;
        if (c < span) v = fmaxf(sb[k] + pr[(size_t)c * DH + k], 0.f);
        xT[k * PADW + c] = v;
    }
    __syncthreads();

    const int f0 = (t & 31) * 4, c0t = (t >> 5) * 16;
    ull_t acc[4][8];

    // GEMM1: x2 = relu(x1 @ W2 + b2)
    acc_init16(acc, b2s, f0);
    gemm_accum16<64>(xT, wch, acc, f0, c0t);
    __syncthreads();
    for (int e = t; e < 64 * DH; e += 256) wch[e] = W2[64 * DH + e];
    __syncthreads();
    gemm_accum16<64>(xT + 64 * PADW, wch, acc, f0, c0t);
    __syncthreads();

    #pragma unroll
    for (int p = 0; p < 8; p++) {
        int c = c0t + 2 * p;
        #pragma unroll
        for (int i = 0; i < 4; i++) {
            float lo, hi; upk(acc[i][p], lo, hi);
            *(float2*)(xT + (f0 + i) * PADW + c) = make_float2(fmaxf(lo, 0.f), fmaxf(hi, 0.f));
        }
    }
    for (int e = t; e < 64 * H; e += 256) {
        int k = e / H, f = e - k * H;
        wch[k * DH + f]     = Wl[e];
        wch[k * DH + H + f] = Wr[e];
    }
    __syncthreads();

    // GEMM2: y = (x2@Wl + bg | x2@Wr)
    acc_init16(acc, bgs, f0);
    gemm_accum16<64>(xT, wch, acc, f0, c0t);
    __syncthreads();
    for (int e = t; e < 64 * H; e += 256) {
        int k = e / H, f = e - k * H;
        wch[k * DH + f]     = Wl[(64 + k) * H + f];
        wch[k * DH + H + f] = Wr[(64 + k) * H + f];
    }
    __syncthreads();
    gemm_accum16<64>(xT + 64 * PADW, wch, acc, f0, c0t);

    float* yb = g_bufB + ((size_t)n * NC + c0b) * DH;
    gemm_epi16_gmem(acc, yb, f0, c0t, span, false);
}

// ============================================================
// SAGE proj (D=64): 128c tile, 4f x 16c, 2 CTAs/SM (R7/R11-proven).
// ============================================================
__global__ void __launch_bounds__(256, 2)
k_sageG64(const float* __restrict__ Wl, const float* __restrict__ Wr, const float* __restrict__ bg) {
    extern __shared__ float sm[];
    float* xT = sm;                // 64*PADW
    float* ws = xT + 64 * PADW;    // 64*128
    float* bs = ws + 64 * DH;      // 128
    const int n = blockIdx.y, c0 = blockIdx.x * CT;
    const int span = min(CT, NC - c0);
    const int t = threadIdx.x;

    if (t < DH) bs[t] = (t < H) ? bg[t] : 0.f;
    for (int e = t; e < 64 * H; e += 256) {
        int k = e / H, f = e - k * H;
        ws[k * DH + f]     = Wl[e];
        ws[k * DH + H + f] = Wr[e];
    }
    const float* xb = g_bufA + ((size_t)n * NC + c0) * 64;
    for (int e = t; e < 64 * CT; e += 256) {
        int c = e >> 6, k = e & 63;
        xT[k * PADW + c] = (c < span) ? xb[e] : 0.f;
    }
    __syncthreads();

    const int f0 = (t & 31) * 4, c0t = (t >> 5) * 16;
    ull_t acc[4][8];
    acc_init16(acc, bs, f0);
    gemm_accum16<64>(xT, ws, acc, f0, c0t);

    float* yb = g_bufB + ((size_t)n * NC + c0) * DH;
    gemm_epi16_gmem(acc, yb, f0, c0t, span, false);
}

// ============================================================
// SAGE aggregate, MLP-8 (R14): edge loop outer, 8 independent float4
// gathers per edge. x' = relu(y[dst][0:64] + mean_src y[src][64:128]).
// ============================================================
__global__ void __launch_bounds__(256)
k_sageA() {
    const int n = blockIdx.y, c0 = blockIdx.x * CT;
    const int span = min(CT, NC - c0);
    const int o0 = g_off[n], o1 = g_off[n + 1];
    const float inv = g_invdeg[n];
    const int tot = span * 16;
    const int t = threadIdx.x;

    const float4* yb = (const float4*)(g_bufB + ((size_t)n * NC + c0) * DH);
    float4* xb = (float4*)(g_bufA + ((size_t)n * NC + c0) * H);

    int cc[8]; int qq[8]; bool val[8];
    float4 own[8]; float4 acc[8];
    #pragma unroll
    for (int j = 0; j < 8; j++) {
        int idx = t + j * 256;
        val[j] = idx < tot;
        cc[j] = idx >> 4;
        qq[j] = idx & 15;
        own[j] = val[j] ? yb[cc[j] * 32 + qq[j]] : make_float4(0.f, 0.f, 0.f, 0.f);
        acc[j] = make_float4(0.f, 0.f, 0.f, 0.f);
    }

    for (int e = o0; e < o1; e++) {
        const float4* src = (const float4*)(g_bufB + ((size_t)g_adj[e] * NC + c0) * DH + H);
        #pragma unroll
        for (int j = 0; j < 8; j++) {
            if (val[j]) {
                float4 v = src[cc[j] * 32 + qq[j]];
                acc[j].x += v.x; acc[j].y += v.y; acc[j].z += v.z; acc[j].w += v.w;
            }
        }
    }

    #pragma unroll
    for (int j = 0; j < 8; j++) {
        if (val[j]) {
            float4 r;
            r.x = fmaxf(own[j].x + acc[j].x * inv, 0.f);
            r.y = fmaxf(own[j].y + acc[j].y * inv, 0.f);
            r.z = fmaxf(own[j].z + acc[j].z * inv, 0.f);
            r.w = fmaxf(own[j].w + acc[j].w * inv, 0.f);
            xb[cc[j] * 16 + qq[j]] = r;
        }
    }
}

// ============================================================
// Pool (max + mean over 40 nodes), L2-normalize, MLP head.
// 50-config tiles, grid (20, NB) = 200 blocks for occupancy.
// ============================================================
__global__ void __launch_bounds__(256)
k_pool(const float* __restrict__ Wp1, const float* __restrict__ bp1,
       const float* __restrict__ Wp2, const float* __restrict__ bp2,
       float* __restrict__ out) {
    __shared__ float pooled[50 * 64];
    __shared__ float w1s[64 * 32];
    __shared__ float b1s[32];
    __shared__ float w2s[32];
    const int b = blockIdx.y, c0 = blockIdx.x * 50;
    const int t = threadIdx.x;
    for (int e = t; e < 64 * 32; e += 256) w1s[e] = Wp1[e];
    if (t < 32) { b1s[t] = bp1[t]; w2s[t] = Wp2[t]; }
    const float invc = g_invcnt[b];
    const float* xb = g_bufA + ((size_t)(b * 40) * NC + c0) * H;
    __syncthreads();
    for (int idx = t; idx < 50 * 64; idx += 256) {
        int c = idx >> 6, h = idx & 63;
        float mx = -3.4e38f, sm_ = 0.f;
        for (int i = 0; i < 40; i++) {
            float v = xb[((size_t)i * NC + c) * H + h];
            mx = fmaxf(mx, v);
            sm_ += v;
        }
        pooled[idx] = mx + sm_ * invc;
    }
    __syncthreads();
    const int w = t >> 5, lane = t & 31;
    const float bp2v = bp2[0];
    for (int c = w; c < 50; c += 8) {
        float v0 = pooled[c * 64 + lane], v1 = pooled[c * 64 + 32 + lane];
        float ss = v0 * v0 + v1 * v1;
        #pragma unroll
        for (int m = 16; m; m >>= 1) ss += __shfl_xor_sync(0xffffffffu, ss, m);
        float inv = rsqrtf(ss);
        float dot = 0.f;
        #pragma unroll
        for (int h = 0; h < 64; h++) dot += pooled[c * 64 + h] * w1s[h * 32 + lane];
        float hj = fmaxf(b1s[lane] + inv * dot, 0.f);
        float o = hj * w2s[lane];
        #pragma unroll
        for (int m = 16; m; m >>= 1) o += __shfl_xor_sync(0xffffffffu, o, m);
        if (lane == 0) out[b * NC + c0 + c] = o + bp2v;
    }
}

// ============================================================
extern "C" void kernel_launch(void* const* d_in, const int* in_sizes, int n_in,
                              void* d_out, int out_size) {
    const float* node_feat   = (const float*)d_in[0];
    const int*   node_opcode = (const int*)d_in[1];
    const float* config_feat = (const float*)d_in[2];
    const int*   edge_index  = (const int*)d_in[3];
    const int*   batch       = (const int*)d_in[4];
    const float* op_emb      = (const float*)d_in[5];
    const float* shape_emb   = (const float*)d_in[6];
    const float* W1  = (const float*)d_in[7];
    const float* b1  = (const float*)d_in[8];
    const float* W2  = (const float*)d_in[9];
    const float* b2  = (const float*)d_in[10];
    const float* Wl0 = (const float*)d_in[11];
    const float* Wr0 = (const float*)d_in[12];
    const float* bg0 = (const float*)d_in[13];
    const float* Wl1 = (const float*)d_in[14];
    const float* Wr1 = (const float*)d_in[15];
    const float* bg1 = (const float*)d_in[16];
    const float* Wl2 = (const float*)d_in[17];
    const float* Wr2 = (const float*)d_in[18];
    const float* bg2 = (const float*)d_in[19];
    const float* Wp1 = (const float*)d_in[20];
    const float* bp1 = (const float*)d_in[21];
    const float* Wp2 = (const float*)d_in[22];
    const float* bp2 = (const float*)d_in[23];
    float* out = (float*)d_out;

    const int SM_L0  = (3 * DH + 128 * PADW + 64 * DH) * 4;   // ~99.5 KB (x2 CTAs)
    const int SM_G64 = (64 * PADW + 64 * DH + DH) * 4;        // ~67 KB (x2 CTAs)
    cudaFuncSetAttribute(k_layer0,  cudaFuncAttributeMaxDynamicSharedMemorySize, SM_L0);
    cudaFuncSetAttribute(k_sageG64, cudaFuncAttributeMaxDynamicSharedMemorySize, SM_G64);

    k_prep<<<1, 512>>>(edge_index, batch);
    k_base<<<NN, 128>>>(node_feat, node_opcode, op_emb, shape_emb, W1, b1);
    k_proj<<<250, 256>>>(config_feat, W1);

    dim3 g128t(8, NN);
    k_layer0<<<g128t, 256, SM_L0>>>(batch, W2, b2, Wl0, Wr0, bg0);  // -> bufB

    k_sageA<<<g128t, 256>>>();                                      // bufB -> bufA
    k_sageG64<<<g128t, 256, SM_G64>>>(Wl1, Wr1, bg1);               // bufA -> bufB
    k_sageA<<<g128t, 256>>>();                                      // bufB -> bufA
    k_sageG64<<<g128t, 256, SM_G64>>>(Wl2, Wr2, bg2);               // bufA -> bufB
    k_sageA<<<g128t, 256>>>();                                      // bufB -> bufA

    dim3 gpool(20, NB);
    k_pool<<<gpool, 256>>>(Wp1, bp1, Wp2, bp2, out);
}

// round 17
// speedup vs baseline: 1.3028x; 1.0252x over previous
#include <cuda_runtime.h>

#define NN 400
#define NC 1000
#define NB 10
#define NE 800
#define XND 121
#define CF 24
#define DH 128
#define H 64
#define CT 128    // configs per tile
#define PADW 132  // padded stride for 128-wide tiles

typedef unsigned long long ull_t;

// ---- scratch ----
__device__ float g_bufA[(size_t)NN * NC * DH];
__device__ float g_bufB[(size_t)NN * NC * DH];
__device__ float g_base[NN * DH];
__device__ float g_proj[(size_t)NB * NC * DH];
__device__ int   g_adj[NE];
__device__ int   g_off[NN + 1];
__device__ float g_invdeg[NN];
__device__ float g_invcnt[NB];

// ---- packed f32x2 helpers ----
__device__ __forceinline__ ull_t pk2(float x) {
    ull_t r; asm("mov.b64 %0, {%1, %1};" : "=l"(r) : "f"(x)); return r;
}
__device__ __forceinline__ ull_t fma2(ull_t a, ull_t b, ull_t c) {
    ull_t d; asm("fma.rn.f32x2 %0, %1, %2, %3;" : "=l"(d) : "l"(a), "l"(b), "l"(c)); return d;
}
__device__ __forceinline__ void upk(ull_t a, float& lo, float& hi) {
    asm("mov.b64 {%0, %1}, %2;" : "=f"(lo), "=f"(hi) : "l"(a));
}

// ============================================================
// Wide GEMM accumulate: 4f x 16c thread tile, DCHUNK k-steps.
// f0 = lane*4, c0t = warp*16 (8 warps -> 128 configs). xT stride PADW.
// ============================================================
template<int DCHUNK>
__device__ __forceinline__ void gemm_accum16(const float* __restrict__ xT,
                                             const float* __restrict__ ws,
                                             ull_t (&acc)[4][8], int f0, int c0t) {
    #pragma unroll 4
    for (int k = 0; k < DCHUNK; k++) {
        float4 wv = *(const float4*)(ws + k * DH + f0);
        ull_t w0 = pk2(wv.x), w1 = pk2(wv.y), w2 = pk2(wv.z), w3 = pk2(wv.w);
        const ulonglong2* xr = (const ulonglong2*)(xT + k * PADW + c0t);
        #pragma unroll
        for (int q = 0; q < 4; q++) {
            ulonglong2 xv = xr[q];
            acc[0][2*q]   = fma2(xv.x, w0, acc[0][2*q]);
            acc[1][2*q]   = fma2(xv.x, w1, acc[1][2*q]);
            acc[2][2*q]   = fma2(xv.x, w2, acc[2][2*q]);
            acc[3][2*q]   = fma2(xv.x, w3, acc[3][2*q]);
            acc[0][2*q+1] = fma2(xv.y, w0, acc[0][2*q+1]);
            acc[1][2*q+1] = fma2(xv.y, w1, acc[1][2*q+1]);
            acc[2][2*q+1] = fma2(xv.y, w2, acc[2][2*q+1]);
            acc[3][2*q+1] = fma2(xv.y, w3, acc[3][2*q+1]);
        }
    }
}

__device__ __forceinline__ void acc_init16(ull_t (&acc)[4][8], const float* bs, int f0) {
    float4 bv = *(const float4*)(bs + f0);
    ull_t b0 = pk2(bv.x), b1 = pk2(bv.y), b2_ = pk2(bv.z), b3 = pk2(bv.w);
    #pragma unroll
    for (int p = 0; p < 8; p++) { acc[0][p] = b0; acc[1][p] = b1; acc[2][p] = b2_; acc[3][p] = b3; }
}

__device__ __forceinline__ void gemm_epi16_gmem(ull_t (&acc)[4][8], float* __restrict__ outg,
                                                int f0, int c0t, int span, bool relu) {
    #pragma unroll
    for (int p = 0; p < 8; p++) {
        int c = c0t + 2 * p;
        float lo0, hi0, lo1, hi1, lo2, hi2, lo3, hi3;
        upk(acc[0][p], lo0, hi0); upk(acc[1][p], lo1, hi1);
        upk(acc[2][p], lo2, hi2); upk(acc[3][p], lo3, hi3);
        if (relu) {
            lo0 = fmaxf(lo0, 0.f); hi0 = fmaxf(hi0, 0.f);
            lo1 = fmaxf(lo1, 0.f); hi1 = fmaxf(hi1, 0.f);
            lo2 = fmaxf(lo2, 0.f); hi2 = fmaxf(hi2, 0.f);
            lo3 = fmaxf(lo3, 0.f); hi3 = fmaxf(hi3, 0.f);
        }
        if (c < span)     *(float4*)(outg + (size_t)c * DH + f0)       = make_float4(lo0, lo1, lo2, lo3);
        if (c + 1 < span) *(float4*)(outg + (size_t)(c + 1) * DH + f0) = make_float4(hi0, hi1, hi2, hi3);
    }
}

// ============================================================
// Setup kernels
// ============================================================
__global__ void k_prep(const int* __restrict__ ei, const int* __restrict__ batch) {
    __shared__ int cnt[NN];
    __shared__ int off[NN + 1];
    __shared__ int cur[NN];
    __shared__ int bc[NB];
    int t = threadIdx.x;
    for (int i = t; i < NN; i += blockDim.x) cnt[i] = 0;
    if (t < NB) bc[t] = 0;
    __syncthreads();
    for (int e = t; e < NE; e += blockDim.x) atomicAdd(&cnt[ei[NE + e]], 1);
    for (int i = t; i < NN; i += blockDim.x) atomicAdd(&bc[batch[i]], 1);
    __syncthreads();
    if (t == 0) {
        int s = 0;
        for (int i = 0; i < NN; i++) { off[i] = s; s += cnt[i]; }
        off[NN] = s;
    }
    __syncthreads();
    for (int i = t; i < NN; i += blockDim.x) {
        cur[i] = off[i];
        g_off[i] = off[i];
        g_invdeg[i] = 1.f / fmaxf((float)cnt[i], 1.f);
    }
    if (t == 0) g_off[NN] = off[NN];
    if (t < NB) g_invcnt[t] = 1.f / fmaxf((float)bc[t], 1.f);
    __syncthreads();
    for (int e = t; e < NE; e += blockDim.x) {
        int d = ei[NE + e];
        int p = atomicAdd(&cur[d], 1);
        g_adj[p] = ei[e];
    }
}

__global__ void k_base(const float* __restrict__ node_feat, const int* __restrict__ opcode,
                       const float* __restrict__ op_emb, const float* __restrict__ shape_emb,
                       const float* __restrict__ W1, const float* __restrict__ b1) {
    __shared__ float xns[XND];
    int n = blockIdx.x, t = threadIdx.x;
    if (t < XND) {
        float v;
        if (t < 85) v = node_feat[n * 86 + t];
        else if (t < 89) { int st = (int)node_feat[n * 86 + 85]; v = shape_emb[st * 4 + (t - 85)]; }
        else v = op_emb[opcode[n] * 32 + (t - 89)];
        xns[t] = v;
    }
    __syncthreads();
    float acc = b1[t];
    #pragma unroll 11
    for (int k = 0; k < XND; k++) acc += xns[k] * W1[k * DH + t];
    g_base[n * DH + t] = acc;
}

__global__ void __launch_bounds__(256)
k_proj(const float* __restrict__ cfgf, const float* __restrict__ W1) {
    __shared__ float w1t[CF * DH];
    __shared__ float cfgs[40 * CF];
    const int r0 = blockIdx.x * 40;
    const int t = threadIdx.x;
    for (int e = t; e < CF * DH; e += 256) w1t[e] = W1[XND * DH + e];
    for (int e = t; e < 40 * CF; e += 256) cfgs[e] = cfgf[(size_t)r0 * CF + e];
    __syncthreads();
    const int f = t & 127, rh = t >> 7;
    for (int rr = rh; rr < 40; rr += 2) {
        float acc = 0.f;
        #pragma unroll
        for (int j = 0; j < CF; j++) acc += cfgs[rr * CF + j] * w1t[j * DH + f];
        g_proj[(size_t)(r0 + rr) * DH + f] = acc;
    }
}

// ============================================================
// FUSED layer 0 (128c tile, 4f x 16c, 2 CTAs/SM) — R12-measured 589us.
// ============================================================
__global__ void __launch_bounds__(256, 2)
k_layer0(const int* __restrict__ batch, const float* __restrict__ W2, const float* __restrict__ b2,
         const float* __restrict__ Wl, const float* __restrict__ Wr, const float* __restrict__ bg) {
    extern __shared__ float sm[];
    float* sb  = sm;                   // 128 base
    float* b2s = sm + DH;              // 128
    float* bgs = sm + 2 * DH;          // 128 (bg | 0)
    float* xT  = sm + 3 * DH;          // 128*PADW (x1, later x2)
    float* wch = xT + 128 * PADW;      // 64*128

    const int n = blockIdx.y, c0b = blockIdx.x * CT;
    const int span = min(CT, NC - c0b);
    const int t = threadIdx.x;

    if (t < DH) {
        sb[t]  = g_base[n * DH + t];
        b2s[t] = b2[t];
        bgs[t] = (t < H) ? bg[t] : 0.f;
    }
    for (int e = t; e < 64 * DH; e += 256) wch[e] = W2[e];
    const int bn = batch[n];
    const float* pr = g_proj + ((size_t)bn * NC + c0b) * DH;
    __syncthreads();
    for (int e = t; e < 128 * CT; e += 256) {
        int c = e >> 7, k = e & 127;
        float v = 0.f;
        if (c < span) v = fmaxf(sb[k] + pr[(size_t)c * DH + k], 0.f);
        xT[k * PADW + c] = v;
    }
    __syncthreads();

    const int f0 = (t & 31) * 4, c0t = (t >> 5) * 16;
    ull_t acc[4][8];

    // GEMM1: x2 = relu(x1 @ W2 + b2)
    acc_init16(acc, b2s, f0);
    gemm_accum16<64>(xT, wch, acc, f0, c0t);
    __syncthreads();
    for (int e = t; e < 64 * DH; e += 256) wch[e] = W2[64 * DH + e];
    __syncthreads();
    gemm_accum16<64>(xT + 64 * PADW, wch, acc, f0, c0t);
    __syncthreads();

    #pragma unroll
    for (int p = 0; p < 8; p++) {
        int c = c0t + 2 * p;
        #pragma unroll
        for (int i = 0; i < 4; i++) {
            float lo, hi; upk(acc[i][p], lo, hi);
            *(float2*)(xT + (f0 + i) * PADW + c) = make_float2(fmaxf(lo, 0.f), fmaxf(hi, 0.f));
        }
    }
    for (int e = t; e < 64 * H; e += 256) {
        int k = e / H, f = e - k * H;
        wch[k * DH + f]     = Wl[e];
        wch[k * DH + H + f] = Wr[e];
    }
    __syncthreads();

    // GEMM2: y = (x2@Wl + bg | x2@Wr)
    acc_init16(acc, bgs, f0);
    gemm_accum16<64>(xT, wch, acc, f0, c0t);
    __syncthreads();
    for (int e = t; e < 64 * H; e += 256) {
        int k = e / H, f = e - k * H;
        wch[k * DH + f]     = Wl[(64 + k) * H + f];
        wch[k * DH + H + f] = Wr[(64 + k) * H + f];
    }
    __syncthreads();
    gemm_accum16<64>(xT + 64 * PADW, wch, acc, f0, c0t);

    float* yb = g_bufB + ((size_t)n * NC + c0b) * DH;
    gemm_epi16_gmem(acc, yb, f0, c0t, span, false);
}

// ============================================================
// FUSED SAGE layer (agg + proj), MLP-8 gather fill:
// x[k][c] = relu(in[n][c][k] + invdeg*sum_src in[src][c][64+k]) -> smem,
// then y = (x@Wl + bg | x@Wr) -> out. 128c tile, 2 CTAs/SM.
// BtoA: in=g_bufB, out=g_bufA; else in=g_bufA, out=g_bufB.
// ============================================================
template<bool BtoA>
__global__ void __launch_bounds__(256, 2)
k_sageL(const float* __restrict__ Wl, const float* __restrict__ Wr, const float* __restrict__ bg) {
    extern __shared__ float sm[];
    float* xT = sm;                // 64*PADW
    float* ws = xT + 64 * PADW;    // 64*128
    float* bs = ws + 64 * DH;      // 128
    const int n = blockIdx.y, c0 = blockIdx.x * CT;
    const int span = min(CT, NC - c0);
    const int t = threadIdx.x;
    const float* in  = BtoA ? g_bufB : g_bufA;
    float*       out = BtoA ? g_bufA : g_bufB;

    if (t < DH) bs[t] = (t < H) ? bg[t] : 0.f;
    for (int e = t; e < 64 * H; e += 256) {
        int k = e / H, f = e - k * H;
        ws[k * DH + f]     = Wl[e];
        ws[k * DH + H + f] = Wr[e];
    }

    // fused aggregate fill (MLP-8): idx -> (c = idx>>4, quad q = idx&15)
    {
        const int o0 = g_off[n], o1 = g_off[n + 1];
        const float inv = g_invdeg[n];
        float4 acc[8];
        #pragma unroll
        for (int j = 0; j < 8; j++) acc[j] = make_float4(0.f, 0.f, 0.f, 0.f);

        for (int e = o0; e < o1; e++) {
            const float* srcb = in + ((size_t)g_adj[e] * NC + c0) * DH + H;
            #pragma unroll
            for (int j = 0; j < 8; j++) {
                int idx = t + j * 256;
                int c = idx >> 4, q = idx & 15;
                if (c < span) {
                    float4 v = *(const float4*)(srcb + (size_t)c * DH + 4 * q);
                    acc[j].x += v.x; acc[j].y += v.y; acc[j].z += v.z; acc[j].w += v.w;
                }
            }
        }
        const float* ownb = in + ((size_t)n * NC + c0) * DH;
        #pragma unroll
        for (int j = 0; j < 8; j++) {
            int idx = t + j * 256;
            int c = idx >> 4, q = idx & 15;
            float4 r = make_float4(0.f, 0.f, 0.f, 0.f);
            if (c < span) {
                float4 own = *(const float4*)(ownb + (size_t)c * DH + 4 * q);
                r.x = fmaxf(own.x + acc[j].x * inv, 0.f);
                r.y = fmaxf(own.y + acc[j].y * inv, 0.f);
                r.z = fmaxf(own.z + acc[j].z * inv, 0.f);
                r.w = fmaxf(own.w + acc[j].w * inv, 0.f);
            }
            int kb = 4 * q;
            xT[(kb + 0) * PADW + c] = r.x;
            xT[(kb + 1) * PADW + c] = r.y;
            xT[(kb + 2) * PADW + c] = r.z;
            xT[(kb + 3) * PADW + c] = r.w;
        }
    }
    __syncthreads();

    const int f0 = (t & 31) * 4, c0t = (t >> 5) * 16;
    ull_t acc[4][8];
    acc_init16(acc, bs, f0);
    gemm_accum16<64>(xT, ws, acc, f0, c0t);

    float* yb = out + ((size_t)n * NC + c0) * DH;
    gemm_epi16_gmem(acc, yb, f0, c0t, span, false);
}

// ============================================================
// SAGE aggregate, MLP-8 (R14): final layer, bufB -> bufA [n][c][64].
// ============================================================
__global__ void __launch_bounds__(256)
k_sageA() {
    const int n = blockIdx.y, c0 = blockIdx.x * CT;
    const int span = min(CT, NC - c0);
    const int o0 = g_off[n], o1 = g_off[n + 1];
    const float inv = g_invdeg[n];
    const int tot = span * 16;
    const int t = threadIdx.x;

    const float4* yb = (const float4*)(g_bufB + ((size_t)n * NC + c0) * DH);
    float4* xb = (float4*)(g_bufA + ((size_t)n * NC + c0) * H);

    int cc[8]; int qq[8]; bool val[8];
    float4 acc[8];
    #pragma unroll
    for (int j = 0; j < 8; j++) {
        int idx = t + j * 256;
        val[j] = idx < tot;
        cc[j] = idx >> 4;
        qq[j] = idx & 15;
        acc[j] = make_float4(0.f, 0.f, 0.f, 0.f);
    }

    for (int e = o0; e < o1; e++) {
        const float4* src = (const float4*)(g_bufB + ((size_t)g_adj[e] * NC + c0) * DH + H);
        #pragma unroll
        for (int j = 0; j < 8; j++) {
            if (val[j]) {
                float4 v = src[cc[j] * 32 + qq[j]];
                acc[j].x += v.x; acc[j].y += v.y; acc[j].z += v.z; acc[j].w += v.w;
            }
        }
    }

    #pragma unroll
    for (int j = 0; j < 8; j++) {
        if (val[j]) {
            float4 own = yb[cc[j] * 32 + qq[j]];
            float4 r;
            r.x = fmaxf(own.x + acc[j].x * inv, 0.f);
            r.y = fmaxf(own.y + acc[j].y * inv, 0.f);
            r.z = fmaxf(own.z + acc[j].z * inv, 0.f);
            r.w = fmaxf(own.w + acc[j].w * inv, 0.f);
            xb[cc[j] * 16 + qq[j]] = r;
        }
    }
}

// ============================================================
// Pool (max + mean over 40 nodes), L2-normalize, MLP head.
// 50-config tiles, grid (20, NB).
// ============================================================
__global__ void __launch_bounds__(256)
k_pool(const float* __restrict__ Wp1, const float* __restrict__ bp1,
       const float* __restrict__ Wp2, const float* __restrict__ bp2,
       float* __restrict__ out) {
    __shared__ float pooled[50 * 64];
    __shared__ float w1s[64 * 32];
    __shared__ float b1s[32];
    __shared__ float w2s[32];
    const int b = blockIdx.y, c0 = blockIdx.x * 50;
    const int t = threadIdx.x;
    for (int e = t; e < 64 * 32; e += 256) w1s[e] = Wp1[e];
    if (t < 32) { b1s[t] = bp1[t]; w2s[t] = Wp2[t]; }
    const float invc = g_invcnt[b];
    const float* xb = g_bufA + ((size_t)(b * 40) * NC + c0) * H;
    __syncthreads();
    for (int idx = t; idx < 50 * 64; idx += 256) {
        int c = idx >> 6, h = idx & 63;
        float mx = -3.4e38f, sm_ = 0.f;
        for (int i = 0; i < 40; i++) {
            float v = xb[((size_t)i * NC + c) * H + h];
            mx = fmaxf(mx, v);
            sm_ += v;
        }
        pooled[idx] = mx + sm_ * invc;
    }
    __syncthreads();
    const int w = t >> 5, lane = t & 31;
    const float bp2v = bp2[0];
    for (int c = w; c < 50; c += 8) {
        float v0 = pooled[c * 64 + lane], v1 = pooled[c * 64 + 32 + lane];
        float ss = v0 * v0 + v1 * v1;
        #pragma unroll
        for (int m = 16; m; m >>= 1) ss += __shfl_xor_sync(0xffffffffu, ss, m);
        float inv = rsqrtf(ss);
        float dot = 0.f;
        #pragma unroll
        for (int h = 0; h < 64; h++) dot += pooled[c * 64 + h] * w1s[h * 32 + lane];
        float hj = fmaxf(b1s[lane] + inv * dot, 0.f);
        float o = hj * w2s[lane];
        #pragma unroll
        for (int m = 16; m; m >>= 1) o += __shfl_xor_sync(0xffffffffu, o, m);
        if (lane == 0) out[b * NC + c0 + c] = o + bp2v;
    }
}

// ============================================================
extern "C" void kernel_launch(void* const* d_in, const int* in_sizes, int n_in,
                              void* d_out, int out_size) {
    const float* node_feat   = (const float*)d_in[0];
    const int*   node_opcode = (const int*)d_in[1];
    const float* config_feat = (const float*)d_in[2];
    const int*   edge_index  = (const int*)d_in[3];
    const int*   batch       = (const int*)d_in[4];
    const float* op_emb      = (const float*)d_in[5];
    const float* shape_emb   = (const float*)d_in[6];
    const float* W1  = (const float*)d_in[7];
    const float* b1  = (const float*)d_in[8];
    const float* W2  = (const float*)d_in[9];
    const float* b2  = (const float*)d_in[10];
    const float* Wl0 = (const float*)d_in[11];
    const float* Wr0 = (const float*)d_in[12];
    const float* bg0 = (const float*)d_in[13];
    const float* Wl1 = (const float*)d_in[14];
    const float* Wr1 = (const float*)d_in[15];
    const float* bg1 = (const float*)d_in[16];
    const float* Wl2 = (const float*)d_in[17];
    const float* Wr2 = (const float*)d_in[18];
    const float* bg2 = (const float*)d_in[19];
    const float* Wp1 = (const float*)d_in[20];
    const float* bp1 = (const float*)d_in[21];
    const float* Wp2 = (const float*)d_in[22];
    const float* bp2 = (const float*)d_in[23];
    float* out = (float*)d_out;

    const int SM_L0 = (3 * DH + 128 * PADW + 64 * DH) * 4;   // ~99.5 KB (x2 CTAs)
    const int SM_SL = (64 * PADW + 64 * DH + DH) * 4;        // ~67 KB (x2 CTAs)
    cudaFuncSetAttribute(k_layer0,       cudaFuncAttributeMaxDynamicSharedMemorySize, SM_L0);
    cudaFuncSetAttribute(k_sageL<true>,  cudaFuncAttributeMaxDynamicSharedMemorySize, SM_SL);
    cudaFuncSetAttribute(k_sageL<false>, cudaFuncAttributeMaxDynamicSharedMemorySize, SM_SL);

    k_prep<<<1, 512>>>(edge_index, batch);
    k_base<<<NN, 128>>>(node_feat, node_opcode, op_emb, shape_emb, W1, b1);
    k_proj<<<250, 256>>>(config_feat, W1);

    dim3 g128t(8, NN);
    k_layer0<<<g128t, 256, SM_L0>>>(batch, W2, b2, Wl0, Wr0, bg0);  // -> bufB

    k_sageL<true><<<g128t, 256, SM_SL>>>(Wl1, Wr1, bg1);            // agg bufB -> proj -> bufA
    k_sageL<false><<<g128t, 256, SM_SL>>>(Wl2, Wr2, bg2);           // agg bufA -> proj -> bufB
    k_sageA<<<g128t, 256>>>();                                      // agg bufB -> bufA

    dim3 gpool(20, NB);
    k_pool<<<gpool, 256>>>(Wp1, bp1, Wp2, bp2, out);
}